// round 11
// baseline (speedup 1.0000x reference)
#include <cuda_runtime.h>
#include <cuda_bf16.h>

// Problem constants
#define BB 8
#define CC 64
#define HP 32
#define WP 32
#define NN 1024          // HP*WP
#define NHEADS 16
// scale * log2(e) = 0.5 * 1.4426950408889634
#define ALPHA 0.72134752044448169f

// Scratch (no cudaMalloc allowed) — float4 for 16B alignment
__device__ float4 g_q4[BB * NHEADS * NN];      // [b][h][n][4], q pre-scaled by ALPHA
__device__ float4 g_k4[BB * NHEADS * NN];
__device__ float4 g_v4[BB * NHEADS * NN];
__device__ float4 g_o4[BB * NN * NHEADS];      // [b][n][h][4] == (B,N,64)
__device__ unsigned char g_idx[BB * CC * NN];  // argmax within 2x2 window

typedef unsigned long long ull;

// ---- packed fp32 (f32x2) helpers ----
__device__ __forceinline__ ull pack2(float a, float b) {
    ull r;
    asm("mov.b64 %0, {%1,%2};" : "=l"(r) : "f"(a), "f"(b));
    return r;
}
__device__ __forceinline__ void unpack2(ull p, float& a, float& b) {
    asm("mov.b64 {%0,%1}, %2;" : "=f"(a), "=f"(b) : "l"(p));
}
__device__ __forceinline__ ull mul2(ull a, ull b) {
    ull r;
    asm("mul.rn.f32x2 %0, %1, %2;" : "=l"(r) : "l"(a), "l"(b));
    return r;
}
__device__ __forceinline__ ull add2(ull a, ull b) {
    ull r;
    asm("add.rn.f32x2 %0, %1, %2;" : "=l"(r) : "l"(a), "l"(b));
    return r;
}
__device__ __forceinline__ ull fma2(ull a, ull b, ull c) {
    ull r;
    asm("fma.rn.f32x2 %0, %1, %2, %3;" : "=l"(r) : "l"(a), "l"(b), "l"(c));
    return r;
}
__device__ __forceinline__ float ex2f(float x) {
    float r;
    asm("ex2.approx.f32 %0, %1;" : "=f"(r) : "f"(x));
    return r;
}

// ---------------------------------------------------------------------------
// Kernel A: 2x2 maxpool + argmax, then qkv = t @ w_qkv (64 x 192).
// grid 512 = (b, hp, colhalf), 256 threads. Block = 32 n x 96 cols;
// thread = 1 n x 12 cols, packed FFMA2 (6 fma2 per c). Small equal blocks
// (3.46 waves, multi-resident) to avoid the 1.73-wave quantization of R10.
// ---------------------------------------------------------------------------
__global__ __launch_bounds__(256) void kA(const float* __restrict__ x,
                                          const float* __restrict__ wq) {
    __shared__ float wsm[64 * 96];  // [c][j], 24KB
    __shared__ float tsm[64 * 32];  // [c][wp], 8KB
    const int tid = threadIdx.x;
    const int blk = blockIdx.x;
    const int half = blk & 1;
    const int hp = (blk >> 1) & 31;
    const int b = blk >> 6;

    // Stage weight half: 64 rows x 96 floats = 1536 float4, coalesced.
#pragma unroll
    for (int s = 0; s < 6; s++) {
        int idx = tid + s * 256;
        int c = idx / 24, j4 = idx % 24;
        *(float4*)&wsm[c * 96 + j4 * 4] =
            *(const float4*)(wq + c * 192 + half * 96 + j4 * 4);
    }

    // Pooling: 64 c x 32 wp = 2048 units, 8 per thread.
#pragma unroll
    for (int s = 0; s < 8; s++) {
        int p = tid + s * 256;
        int c = p >> 5, wp = p & 31;
        const float* base = x + (((b * 64 + c) * 64 + 2 * hp) * 64 + 2 * wp);
        float2 a  = *(const float2*)(base);
        float2 d2 = *(const float2*)(base + 64);
        float best = a.x; int bi = 0;
        if (a.y  > best) { best = a.y;  bi = 1; }
        if (d2.x > best) { best = d2.x; bi = 2; }
        if (d2.y > best) { best = d2.y; bi = 3; }
        tsm[c * 32 + wp] = best;
        if (half == 0)
            g_idx[(b * 64 + c) * 1024 + hp * 32 + wp] = (unsigned char)bi;
    }
    __syncthreads();

    // GEMM: thread = (wp, colg); 12 cols (6 packed) per thread, all SMEM.
    const int wp = tid >> 3;            // 32 n
    const int colg = tid & 7;           // 8 groups x 12 cols = 96
    ull acc[6];
#pragma unroll
    for (int j = 0; j < 6; j++) acc[j] = 0ull;

#pragma unroll 4
    for (int c = 0; c < 64; c++) {
        float tv = tsm[c * 32 + wp];
        ull tvp = pack2(tv, tv);
        const ulonglong2* wrow = (const ulonglong2*)&wsm[c * 96 + colg * 12];
        ulonglong2 w0 = wrow[0], w1 = wrow[1], w2 = wrow[2];
        acc[0] = fma2(tvp, w0.x, acc[0]);
        acc[1] = fma2(tvp, w0.y, acc[1]);
        acc[2] = fma2(tvp, w1.x, acc[2]);
        acc[3] = fma2(tvp, w1.y, acc[3]);
        acc[4] = fma2(tvp, w2.x, acc[4]);
        acc[5] = fma2(tvp, w2.y, acc[5]);
    }

    // Epilogue: 3 float4 stores (each 4-col group = one head's 4 dims).
    const int n = hp * 32 + wp;
#pragma unroll
    for (int g = 0; g < 3; g++) {
        float a0, a1, a2, a3;
        unpack2(acc[2 * g], a0, a1);
        unpack2(acc[2 * g + 1], a2, a3);
        int col = half * 96 + colg * 12 + g * 4;   // multiple of 4
        int sp = col >> 6;
        int hh = (col & 63) >> 2;
        int off = (b * 16 + hh) * 1024 + n;
        if (sp == 0) {
            g_q4[off] = make_float4(a0 * ALPHA, a1 * ALPHA, a2 * ALPHA, a3 * ALPHA);
        } else if (sp == 1) {
            g_k4[off] = make_float4(a0, a1, a2, a3);
        } else {
            g_v4[off] = make_float4(a0, a1, a2, a3);
        }
    }
}

// ---------------------------------------------------------------------------
// Kernel B: attention. grid 2048 = (b,h) x 16 query-chunks of 64, 128
// threads: 2 threads per query, m-split in half (512 keys each), combined
// with one shfl_xor. Small equal blocks -> ~7 co-resident per SM, fills
// overlap sibling compute, fine-grained balance over all 148 SMs.
// K/V m-pair-interleaved in smem; max-free exp2 softmax; packed fma.rn.f32x2.
// ---------------------------------------------------------------------------
__global__ __launch_bounds__(128) void kB() {
    __shared__ float4 ksmA[512], ksmB[512];
    __shared__ float4 vsmA[512], vsmB[512];
    const int tid = threadIdx.x;
    const int blk = blockIdx.x;
    const int bh = blk >> 4;          // 0..127  (b*16 + h)
    const int qc = blk & 15;          // query chunk

    const float4* kg = g_k4 + bh * 1024;
    const float4* vg = g_v4 + bh * 1024;
#pragma unroll
    for (int s = 0; s < 4; s++) {
        int e = tid + s * 128;
        float4 k0 = kg[2 * e], k1 = kg[2 * e + 1];
        ksmA[e] = make_float4(k0.x, k1.x, k0.y, k1.y);
        ksmB[e] = make_float4(k0.z, k1.z, k0.w, k1.w);
        float4 v0 = vg[2 * e], v1 = vg[2 * e + 1];
        vsmA[e] = make_float4(v0.x, v1.x, v0.y, v1.y);
        vsmB[e] = make_float4(v0.z, v1.z, v0.w, v1.w);
    }

    const int qloc = tid >> 1;        // 0..63
    const int half = tid & 1;         // m-slice
    const int nq = qc * 64 + qloc;
    float4 q0 = ((const float4*)g_q4)[bh * 1024 + nq];
    ull qx = pack2(q0.x, q0.x), qy = pack2(q0.y, q0.y);
    ull qz = pack2(q0.z, q0.z), qw = pack2(q0.w, q0.w);
    __syncthreads();

    ull s0 = 0ull, ax0 = 0ull, ay0 = 0ull, az0 = 0ull, aw0 = 0ull;
    const int mp0 = half * 256;

#pragma unroll 4
    for (int i = 0; i < 256; i++) {
        int mp = mp0 + i;
        ulonglong2 ka = *(const ulonglong2*)&ksmA[mp];  // kx pair, ky pair
        ulonglong2 kb = *(const ulonglong2*)&ksmB[mp];  // kz pair, kw pair

        ull d0 = mul2(qx, ka.x);
        d0 = fma2(qy, ka.y, d0);
        d0 = fma2(qz, kb.x, d0);
        d0 = fma2(qw, kb.y, d0);

        float d0e, d0o;
        unpack2(d0, d0e, d0o);
        ull e0 = pack2(ex2f(d0e), ex2f(d0o));

        ulonglong2 va = *(const ulonglong2*)&vsmA[mp];
        ulonglong2 vb = *(const ulonglong2*)&vsmB[mp];

        s0  = add2(s0, e0);
        ax0 = fma2(e0, va.x, ax0);
        ay0 = fma2(e0, va.y, ay0);
        az0 = fma2(e0, vb.x, az0);
        aw0 = fma2(e0, vb.y, aw0);
    }

    // reduce packed lanes, then combine the two m-halves (adjacent lanes)
    float e, o;
    unpack2(s0, e, o);  float s  = e + o;
    unpack2(ax0, e, o); float ox = e + o;
    unpack2(ay0, e, o); float oy = e + o;
    unpack2(az0, e, o); float oz = e + o;
    unpack2(aw0, e, o); float ow = e + o;

    s  += __shfl_xor_sync(0xffffffffu, s, 1);
    ox += __shfl_xor_sync(0xffffffffu, ox, 1);
    oy += __shfl_xor_sync(0xffffffffu, oy, 1);
    oz += __shfl_xor_sync(0xffffffffu, oz, 1);
    ow += __shfl_xor_sync(0xffffffffu, ow, 1);

    if (half == 0) {
        float r = 1.0f / s;
        int b = bh >> 4, h = bh & 15;
        g_o4[(b * 1024 + nq) * 16 + h] =
            make_float4(ox * r, oy * r, oz * r, ow * r);
    }
}

// ---------------------------------------------------------------------------
// Kernel C: o @ w_proj (64x64) + BN affine + argmax unpool scatter.
// grid 256 = (b, hp), 256 threads; packed FFMA2 inner loop (4 fma2 per c).
// ---------------------------------------------------------------------------
__global__ __launch_bounds__(256) void kC(const float* __restrict__ wproj,
                                          const float* __restrict__ gamma,
                                          const float* __restrict__ beta,
                                          const float* __restrict__ bmean,
                                          const float* __restrict__ bvar,
                                          float* __restrict__ out) {
    __shared__ float wsm[64 * 64];
    __shared__ float osm[32 * 64];   // [wp][c]
    __shared__ float psm[32 * 65];   // [wp][j], padded vs bank conflicts
    __shared__ float invs[64], adds[64];

    const int tid = threadIdx.x;
    const int blk = blockIdx.x;
    const int b = blk >> 5, hp = blk & 31;

#pragma unroll
    for (int s = 0; s < 16; s++) wsm[tid + s * 256] = wproj[tid + s * 256];
    const float* og = (const float*)g_o4 + (b * 1024 + hp * 32) * 64;
#pragma unroll
    for (int s = 0; s < 8; s++) osm[tid + s * 256] = og[tid + s * 256];
    if (tid < 64) {
        float inv = gamma[tid] * rsqrtf(bvar[tid] + 1e-5f);
        invs[tid] = inv;
        adds[tid] = fmaf(-bmean[tid], inv, beta[tid]);
    }
    __syncthreads();

    // proj + affine: thread = (wp, colg); 8 cols (4 packed) per thread.
    {
        const int wp = tid >> 3;
        const int colg = tid & 7;
        ull acc[4];
#pragma unroll
        for (int j = 0; j < 4; j++) acc[j] = 0ull;
#pragma unroll 4
        for (int c = 0; c < 64; c++) {
            float ov = osm[wp * 64 + c];
            ull ovp = pack2(ov, ov);
            const ulonglong2* wrow = (const ulonglong2*)&wsm[c * 64 + colg * 8];
            ulonglong2 w0 = wrow[0], w1 = wrow[1];
            acc[0] = fma2(ovp, w0.x, acc[0]);
            acc[1] = fma2(ovp, w0.y, acc[1]);
            acc[2] = fma2(ovp, w1.x, acc[2]);
            acc[3] = fma2(ovp, w1.y, acc[3]);
        }
#pragma unroll
        for (int j = 0; j < 4; j++) {
            float a0, a1;
            unpack2(acc[j], a0, a1);
            int col = colg * 8 + j * 2;
            psm[wp * 65 + col]     = fmaf(a0, invs[col], adds[col]);
            psm[wp * 65 + col + 1] = fmaf(a1, invs[col + 1], adds[col + 1]);
        }
    }
    __syncthreads();

    // scatter into 2x2 windows (zeros at non-argmax positions)
#pragma unroll
    for (int s = 0; s < 8; s++) {
        int p = tid + s * 256;
        int c = p >> 5, wpx = p & 31;
        float val = psm[wpx * 65 + c];
        unsigned char kk = g_idx[(b * 64 + c) * 1024 + hp * 32 + wpx];
        float2 top = make_float2(kk == 0 ? val : 0.f, kk == 1 ? val : 0.f);
        float2 bot = make_float2(kk == 2 ? val : 0.f, kk == 3 ? val : 0.f);
        float* ob = out + (((b * 64 + c) * 64 + 2 * hp) * 64 + 2 * wpx);
        *(float2*)(ob)      = top;
        *(float2*)(ob + 64) = bot;
    }
}

// ---------------------------------------------------------------------------
extern "C" void kernel_launch(void* const* d_in, const int* in_sizes, int n_in,
                              void* d_out, int out_size) {
    const float* x      = (const float*)d_in[0];
    const float* w_qkv  = (const float*)d_in[1];
    const float* w_proj = (const float*)d_in[2];
    const float* gamma  = (const float*)d_in[3];
    const float* beta   = (const float*)d_in[4];
    const float* bmean  = (const float*)d_in[5];
    const float* bvar   = (const float*)d_in[6];
    float* out = (float*)d_out;

    kA<<<512, 256>>>(x, w_qkv);
    kB<<<2048, 128>>>();
    kC<<<256, 256>>>(w_proj, gamma, beta, bmean, bvar, out);
}

// round 12
// speedup vs baseline: 1.6707x; 1.6707x over previous
#include <cuda_runtime.h>
#include <cuda_bf16.h>

// Problem constants
#define BB 8
#define CC 64
#define HP 32
#define WP 32
#define NN 1024          // HP*WP
#define NHEADS 16
// scale * log2(e) = 0.5 * 1.4426950408889634
#define ALPHA 0.72134752044448169f

// Scratch (no cudaMalloc allowed) — float4 for 16B alignment
__device__ float4 g_q4[BB * NHEADS * NN];      // [b][h][n][4], q pre-scaled by ALPHA
__device__ float4 g_k4[BB * NHEADS * NN];
__device__ float4 g_v4[BB * NHEADS * NN];
__device__ float4 g_o4[BB * NN * NHEADS];      // [b][n][h][4] == (B,N,64)
__device__ unsigned char g_idx[BB * CC * NN];  // argmax within 2x2 window

typedef unsigned long long ull;

// ---- packed fp32 (f32x2) helpers ----
__device__ __forceinline__ ull pack2(float a, float b) {
    ull r;
    asm("mov.b64 %0, {%1,%2};" : "=l"(r) : "f"(a), "f"(b));
    return r;
}
__device__ __forceinline__ void unpack2(ull p, float& a, float& b) {
    asm("mov.b64 {%0,%1}, %2;" : "=f"(a), "=f"(b) : "l"(p));
}
__device__ __forceinline__ ull mul2(ull a, ull b) {
    ull r;
    asm("mul.rn.f32x2 %0, %1, %2;" : "=l"(r) : "l"(a), "l"(b));
    return r;
}
__device__ __forceinline__ ull add2(ull a, ull b) {
    ull r;
    asm("add.rn.f32x2 %0, %1, %2;" : "=l"(r) : "l"(a), "l"(b));
    return r;
}
__device__ __forceinline__ ull fma2(ull a, ull b, ull c) {
    ull r;
    asm("fma.rn.f32x2 %0, %1, %2, %3;" : "=l"(r) : "l"(a), "l"(b), "l"(c));
    return r;
}
__device__ __forceinline__ float ex2f(float x) {
    float r;
    asm("ex2.approx.f32 %0, %1;" : "=f"(r) : "f"(x));
    return r;
}

// ---------------------------------------------------------------------------
// Kernel A: 2x2 maxpool + argmax, then qkv = t @ w_qkv (64 x 192).
// grid 256 = (b, hp-pair, colhalf), 128 threads. Block = 64 n x 96 cols;
// thread = 4 n x 12 cols (24 packed acc). 64B of LDS per 48 FMAs -> LDS no
// longer binding (R10/R11 ncu: L1-bound). Small blocks, high residency.
// ---------------------------------------------------------------------------
__global__ __launch_bounds__(128) void kA(const float* __restrict__ x,
                                          const float* __restrict__ wq) {
    __shared__ float wsm[64 * 96];    // [c][j], 24KB
    __shared__ float4 tsm4[64 * 16];  // [c][ngroup of 4 n], 16KB
    const int tid = threadIdx.x;
    const int blk = blockIdx.x;
    const int half = blk & 1;
    const int hpg = (blk >> 1) & 15;   // hp = hpg*2 + hl
    const int b = blk >> 5;

    // Stage weight half: 64 rows x 96 floats = 1536 float4, coalesced.
#pragma unroll
    for (int s = 0; s < 12; s++) {
        int idx = tid + s * 128;
        int c = idx / 24, j4 = idx % 24;
        *(float4*)&wsm[c * 96 + j4 * 4] =
            *(const float4*)(wq + c * 192 + half * 96 + j4 * 4);
    }

    // Pooling: 64 c x 2 hl x 32 wp = 4096 units, 32 per thread.
    float* tview = (float*)tsm4;
#pragma unroll
    for (int s = 0; s < 32; s++) {
        int p = tid + s * 128;
        int c = p >> 6, r = p & 63;
        int hl = r >> 5, wp = r & 31;
        int hp = hpg * 2 + hl;
        const float* base = x + (((b * 64 + c) * 64 + 2 * hp) * 64 + 2 * wp);
        float2 a  = *(const float2*)(base);
        float2 d2 = *(const float2*)(base + 64);
        float best = a.x; int bi = 0;
        if (a.y  > best) { best = a.y;  bi = 1; }
        if (d2.x > best) { best = d2.x; bi = 2; }
        if (d2.y > best) { best = d2.y; bi = 3; }
        tview[c * 64 + hl * 32 + wp] = best;
        if (half == 0)
            g_idx[(b * 64 + c) * 1024 + hp * 32 + wp] = (unsigned char)bi;
    }
    __syncthreads();

    // GEMM: thread = (ng, colg); 4 n x 12 cols, packed over col-pairs.
    const int ng = tid >> 3;            // 16 groups x 4 n = 64 n
    const int colg = tid & 7;           // 8 groups x 12 cols = 96
    ull acc[24];                        // [n][colpair j] = acc[n*6+j]
#pragma unroll
    for (int j = 0; j < 24; j++) acc[j] = 0ull;

#pragma unroll 4
    for (int c = 0; c < 64; c++) {
        float4 t4 = tsm4[c * 16 + ng];              // 4 n values (LDS.128)
        ull tp0 = pack2(t4.x, t4.x), tp1 = pack2(t4.y, t4.y);
        ull tp2 = pack2(t4.z, t4.z), tp3 = pack2(t4.w, t4.w);
        const ulonglong2* wrow = (const ulonglong2*)&wsm[c * 96 + colg * 12];
        ulonglong2 w0 = wrow[0], w1 = wrow[1], w2 = wrow[2];
        acc[0]  = fma2(tp0, w0.x, acc[0]);
        acc[1]  = fma2(tp0, w0.y, acc[1]);
        acc[2]  = fma2(tp0, w1.x, acc[2]);
        acc[3]  = fma2(tp0, w1.y, acc[3]);
        acc[4]  = fma2(tp0, w2.x, acc[4]);
        acc[5]  = fma2(tp0, w2.y, acc[5]);
        acc[6]  = fma2(tp1, w0.x, acc[6]);
        acc[7]  = fma2(tp1, w0.y, acc[7]);
        acc[8]  = fma2(tp1, w1.x, acc[8]);
        acc[9]  = fma2(tp1, w1.y, acc[9]);
        acc[10] = fma2(tp1, w2.x, acc[10]);
        acc[11] = fma2(tp1, w2.y, acc[11]);
        acc[12] = fma2(tp2, w0.x, acc[12]);
        acc[13] = fma2(tp2, w0.y, acc[13]);
        acc[14] = fma2(tp2, w1.x, acc[14]);
        acc[15] = fma2(tp2, w1.y, acc[15]);
        acc[16] = fma2(tp2, w2.x, acc[16]);
        acc[17] = fma2(tp2, w2.y, acc[17]);
        acc[18] = fma2(tp3, w0.x, acc[18]);
        acc[19] = fma2(tp3, w0.y, acc[19]);
        acc[20] = fma2(tp3, w1.x, acc[20]);
        acc[21] = fma2(tp3, w1.y, acc[21]);
        acc[22] = fma2(tp3, w2.x, acc[22]);
        acc[23] = fma2(tp3, w2.y, acc[23]);
    }

    // Epilogue: per n, 3 float4 stores (each 4-col group = one head's 4 dims).
#pragma unroll
    for (int nl = 0; nl < 4; nl++) {
        int n = hpg * 64 + ng * 4 + nl;
#pragma unroll
        for (int g = 0; g < 3; g++) {
            float a0, a1, a2, a3;
            unpack2(acc[nl * 6 + 2 * g], a0, a1);
            unpack2(acc[nl * 6 + 2 * g + 1], a2, a3);
            int col = half * 96 + colg * 12 + g * 4;   // multiple of 4
            int sp = col >> 6;
            int hh = (col & 63) >> 2;
            int off = (b * 16 + hh) * 1024 + n;
            if (sp == 0) {
                g_q4[off] = make_float4(a0 * ALPHA, a1 * ALPHA, a2 * ALPHA, a3 * ALPHA);
            } else if (sp == 1) {
                g_k4[off] = make_float4(a0, a1, a2, a3);
            } else {
                g_v4[off] = make_float4(a0, a1, a2, a3);
            }
        }
    }
}

// ---------------------------------------------------------------------------
// Kernel B: attention. grid 256 = (b,h,q-half), 256 threads, 2 queries per
// thread (amortizes K/V LDS over 2 dots -> FMA-pipe cleanly binding).
// All lanes read the SAME smem entry per iter (broadcast, conflict-free —
// R11's lane-split caused 2-way bank conflicts). Max-free exp2 softmax,
// packed fma.rn.f32x2 over m-pairs.
// ---------------------------------------------------------------------------
__global__ __launch_bounds__(256) void kB() {
    __shared__ float4 ksmA[512], ksmB[512];
    __shared__ float4 vsmA[512], vsmB[512];
    const int tid = threadIdx.x;
    const int blk = blockIdx.x;
    const int bh = blk >> 1;          // b*16 + h
    const int qh = blk & 1;

    const float4* kg = g_k4 + bh * 1024;
    const float4* vg = g_v4 + bh * 1024;
#pragma unroll
    for (int s = 0; s < 2; s++) {
        int e = tid + s * 256;
        float4 k0 = kg[2 * e], k1 = kg[2 * e + 1];
        ksmA[e] = make_float4(k0.x, k1.x, k0.y, k1.y);
        ksmB[e] = make_float4(k0.z, k1.z, k0.w, k1.w);
        float4 v0 = vg[2 * e], v1 = vg[2 * e + 1];
        vsmA[e] = make_float4(v0.x, v1.x, v0.y, v1.y);
        vsmB[e] = make_float4(v0.z, v1.z, v0.w, v1.w);
    }

    const int nq0 = qh * 512 + tid;
    const int nq1 = nq0 + 256;
    float4 q0 = ((const float4*)g_q4)[bh * 1024 + nq0];
    float4 q1 = ((const float4*)g_q4)[bh * 1024 + nq1];
    ull q0x = pack2(q0.x, q0.x), q0y = pack2(q0.y, q0.y);
    ull q0z = pack2(q0.z, q0.z), q0w = pack2(q0.w, q0.w);
    ull q1x = pack2(q1.x, q1.x), q1y = pack2(q1.y, q1.y);
    ull q1z = pack2(q1.z, q1.z), q1w = pack2(q1.w, q1.w);
    __syncthreads();

    ull s0 = 0ull, ax0 = 0ull, ay0 = 0ull, az0 = 0ull, aw0 = 0ull;
    ull s1 = 0ull, ax1 = 0ull, ay1 = 0ull, az1 = 0ull, aw1 = 0ull;

#pragma unroll 4
    for (int mp = 0; mp < 512; mp++) {
        ulonglong2 ka = *(const ulonglong2*)&ksmA[mp];  // kx pair, ky pair
        ulonglong2 kb = *(const ulonglong2*)&ksmB[mp];  // kz pair, kw pair

        ull d0 = mul2(q0x, ka.x);
        d0 = fma2(q0y, ka.y, d0);
        d0 = fma2(q0z, kb.x, d0);
        d0 = fma2(q0w, kb.y, d0);
        ull d1 = mul2(q1x, ka.x);
        d1 = fma2(q1y, ka.y, d1);
        d1 = fma2(q1z, kb.x, d1);
        d1 = fma2(q1w, kb.y, d1);

        float d0e, d0o, d1e, d1o;
        unpack2(d0, d0e, d0o);
        unpack2(d1, d1e, d1o);
        ull e0 = pack2(ex2f(d0e), ex2f(d0o));
        ull e1 = pack2(ex2f(d1e), ex2f(d1o));

        ulonglong2 va = *(const ulonglong2*)&vsmA[mp];
        ulonglong2 vb = *(const ulonglong2*)&vsmB[mp];

        s0  = add2(s0, e0);
        ax0 = fma2(e0, va.x, ax0);
        ay0 = fma2(e0, va.y, ay0);
        az0 = fma2(e0, vb.x, az0);
        aw0 = fma2(e0, vb.y, aw0);
        s1  = add2(s1, e1);
        ax1 = fma2(e1, va.x, ax1);
        ay1 = fma2(e1, va.y, ay1);
        az1 = fma2(e1, vb.x, az1);
        aw1 = fma2(e1, vb.y, aw1);
    }

    const int b = bh >> 4, h = bh & 15;
    float se, so, xe, xo, ye, yo, ze, zo, we, wo;

    unpack2(s0, se, so);
    float r0 = 1.0f / (se + so);
    unpack2(ax0, xe, xo); unpack2(ay0, ye, yo);
    unpack2(az0, ze, zo); unpack2(aw0, we, wo);
    g_o4[(b * 1024 + nq0) * 16 + h] =
        make_float4((xe + xo) * r0, (ye + yo) * r0, (ze + zo) * r0, (we + wo) * r0);

    unpack2(s1, se, so);
    float r1 = 1.0f / (se + so);
    unpack2(ax1, xe, xo); unpack2(ay1, ye, yo);
    unpack2(az1, ze, zo); unpack2(aw1, we, wo);
    g_o4[(b * 1024 + nq1) * 16 + h] =
        make_float4((xe + xo) * r1, (ye + yo) * r1, (ze + zo) * r1, (we + wo) * r1);
}

// ---------------------------------------------------------------------------
// Kernel C: o @ w_proj (64x64) + BN affine + argmax unpool scatter.
// grid 256 = (b, hp), 256 threads, register-tiled 8 outputs/thread (R10).
// ---------------------------------------------------------------------------
__global__ __launch_bounds__(256) void kC(const float* __restrict__ wproj,
                                          const float* __restrict__ gamma,
                                          const float* __restrict__ beta,
                                          const float* __restrict__ bmean,
                                          const float* __restrict__ bvar,
                                          float* __restrict__ out) {
    __shared__ float wsm[64 * 64];
    __shared__ float osm[32 * 64];   // [wp][c]
    __shared__ float psm[32 * 65];   // [wp][j], padded vs bank conflicts
    __shared__ float invs[64], adds[64];

    const int tid = threadIdx.x;
    const int blk = blockIdx.x;
    const int b = blk >> 5, hp = blk & 31;

#pragma unroll
    for (int s = 0; s < 16; s++) wsm[tid + s * 256] = wproj[tid + s * 256];
    const float* og = (const float*)g_o4 + (b * 1024 + hp * 32) * 64;
#pragma unroll
    for (int s = 0; s < 8; s++) osm[tid + s * 256] = og[tid + s * 256];
    if (tid < 64) {
        float inv = gamma[tid] * rsqrtf(bvar[tid] + 1e-5f);
        invs[tid] = inv;
        adds[tid] = fmaf(-bmean[tid], inv, beta[tid]);
    }
    __syncthreads();

    // proj + affine: thread = (wp, colg); 8 cols per thread in registers.
    {
        const int wp = tid >> 3;
        const int colg = tid & 7;
        float acc[8];
#pragma unroll
        for (int j = 0; j < 8; j++) acc[j] = 0.f;
#pragma unroll 4
        for (int c = 0; c < 64; c++) {
            float ov = osm[wp * 64 + c];
            const float4* wrow = (const float4*)&wsm[c * 64 + colg * 8];
            float4 w0 = wrow[0], w1 = wrow[1];
            acc[0] = fmaf(ov, w0.x, acc[0]);
            acc[1] = fmaf(ov, w0.y, acc[1]);
            acc[2] = fmaf(ov, w0.z, acc[2]);
            acc[3] = fmaf(ov, w0.w, acc[3]);
            acc[4] = fmaf(ov, w1.x, acc[4]);
            acc[5] = fmaf(ov, w1.y, acc[5]);
            acc[6] = fmaf(ov, w1.z, acc[6]);
            acc[7] = fmaf(ov, w1.w, acc[7]);
        }
#pragma unroll
        for (int j = 0; j < 8; j++) {
            int col = colg * 8 + j;
            psm[wp * 65 + col] = fmaf(acc[j], invs[col], adds[col]);
        }
    }
    __syncthreads();

    // scatter into 2x2 windows (zeros at non-argmax positions)
#pragma unroll
    for (int s = 0; s < 8; s++) {
        int p = tid + s * 256;
        int c = p >> 5, wpx = p & 31;
        float val = psm[wpx * 65 + c];
        unsigned char kk = g_idx[(b * 64 + c) * 1024 + hp * 32 + wpx];
        float2 top = make_float2(kk == 0 ? val : 0.f, kk == 1 ? val : 0.f);
        float2 bot = make_float2(kk == 2 ? val : 0.f, kk == 3 ? val : 0.f);
        float* ob = out + (((b * 64 + c) * 64 + 2 * hp) * 64 + 2 * wpx);
        *(float2*)(ob)      = top;
        *(float2*)(ob + 64) = bot;
    }
}

// ---------------------------------------------------------------------------
extern "C" void kernel_launch(void* const* d_in, const int* in_sizes, int n_in,
                              void* d_out, int out_size) {
    const float* x      = (const float*)d_in[0];
    const float* w_qkv  = (const float*)d_in[1];
    const float* w_proj = (const float*)d_in[2];
    const float* gamma  = (const float*)d_in[3];
    const float* beta   = (const float*)d_in[4];
    const float* bmean  = (const float*)d_in[5];
    const float* bvar   = (const float*)d_in[6];
    float* out = (float*)d_out;

    kA<<<256, 128>>>(x, w_qkv);
    kB<<<256, 256>>>();
    kC<<<256, 256>>>(w_proj, gamma, beta, bmean, bvar, out);
}